// round 1
// baseline (speedup 1.0000x reference)
#include <cuda_runtime.h>

#define BB 256
#define II 1152
#define OO 10
#define DDO 16
#define DDI 8
#define OD 160      // OO*DDO
#define IT 32       // i per block
#define NT 36       // II/IT
#define BW 8        // b per block (one per warp)
#define WPAD 12     // smem W row stride (floats), conflict-free for LDS.128

// Scratch (device globals: allocation-free rule)
__device__ float g_hat[(size_t)BB * II * OD];     // 47,185,920 floats (~189 MB)
__device__ float g_spart[(size_t)BB * NT * OD];   // per-(b, i-tile) partial s
__device__ float g_vsum[BB * OD];                 // running sum of v_r

__global__ void __launch_bounds__(1024) k_zero() {
    int idx = blockIdx.x * 1024 + threadIdx.x;
    if (idx < BB * OD) g_vsum[idx] = 0.0f;
}

// K1: hat_u = W @ x per (b,i); write g_hat; accumulate s0 = 0.1 * sum_i hat_u
__global__ void __launch_bounds__(256) k_hat(const float* __restrict__ x,
                                             const float* __restrict__ w) {
    __shared__ float wsm[OD * WPAD];   // 1920 floats
    const int t = threadIdx.x;
    const int warp = t >> 5, lane = t & 31;
    const int og = lane >> 4, d = lane & 15;
    const int i0 = blockIdx.x * IT;
    const int b = blockIdx.y * BW + warp;

    float sacc[5] = {0.f, 0.f, 0.f, 0.f, 0.f};

    for (int ii = 0; ii < IT; ii++) {
        const int i = i0 + ii;
        // stage W[i] (1280 floats) into padded smem
        const float* wp = w + (size_t)i * OD * DDI;
        #pragma unroll
        for (int r = 0; r < 5; r++) {
            int m = t + r * 256;              // 0..1279
            wsm[(m >> 3) * WPAD + (m & 7)] = wp[m];
        }
        __syncthreads();

        const float* xp = x + ((size_t)b * II + i) * DDI;
        const float4 xa = *(const float4*)xp;
        const float4 xb = *(const float4*)(xp + 4);

        float h[5];
        #pragma unroll
        for (int j = 0; j < 5; j++) {
            const int o = og + 2 * j;
            const float* wr = &wsm[(o * DDO + d) * WPAD];
            const float4 wa = *(const float4*)wr;
            const float4 wb = *(const float4*)(wr + 4);
            h[j] = wa.x * xa.x + wa.y * xa.y + wa.z * xa.z + wa.w * xa.w
                 + wb.x * xb.x + wb.y * xb.y + wb.z * xb.z + wb.w * xb.w;
            sacc[j] += h[j];
        }
        // write hat_u row: offset (o*16+d) = 32*j + lane  -> coalesced
        float* hp = g_hat + ((size_t)b * II + i) * OD;
        #pragma unroll
        for (int j = 0; j < 5; j++) hp[j * 32 + lane] = h[j];
        __syncthreads();
    }
    float* sp = g_spart + ((size_t)b * NT + blockIdx.x) * OD;
    #pragma unroll
    for (int j = 0; j < 5; j++) sp[j * 32 + lane] = 0.1f * sacc[j];
}

// K2: one routing pass. logits = hat_u . vsum ; c = softmax_o ; s += c * hat_u
__global__ void __launch_bounds__(256) k_route() {
    __shared__ float vs[BW][OD];
    const int t = threadIdx.x;
    const int warp = t >> 5, lane = t & 31;
    const int b0 = blockIdx.y * BW;
    const int b = b0 + warp;
    const int i0 = blockIdx.x * IT;

    for (int m = t; m < BW * OD; m += 256) vs[m / OD][m % OD] = g_vsum[b0 * OD + m];
    __syncthreads();

    float vv[5];
    #pragma unroll
    for (int j = 0; j < 5; j++) vv[j] = vs[warp][j * 32 + lane];

    float sacc[5] = {0.f, 0.f, 0.f, 0.f, 0.f};

    for (int ii = 0; ii < IT; ii++) {
        const float* hp = g_hat + ((size_t)b * II + (i0 + ii)) * OD;
        float h[5], q[5];
        #pragma unroll
        for (int j = 0; j < 5; j++) h[j] = __ldg(&hp[j * 32 + lane]);
        #pragma unroll
        for (int j = 0; j < 5; j++) q[j] = h[j] * vv[j];
        // reduce over d: 16-lane butterfly within each half (og)
        #pragma unroll
        for (int s = 8; s >= 1; s >>= 1) {
            #pragma unroll
            for (int j = 0; j < 5; j++)
                q[j] += __shfl_xor_sync(0xffffffffu, q[j], s);
        }
        // q[j] = logit for o = og + 2j; fetch the other half's 5 logits
        float oth[5];
        #pragma unroll
        for (int j = 0; j < 5; j++) oth[j] = __shfl_xor_sync(0xffffffffu, q[j], 16);
        float mx = q[0];
        #pragma unroll
        for (int j = 1; j < 5; j++) mx = fmaxf(mx, q[j]);
        #pragma unroll
        for (int j = 0; j < 5; j++) mx = fmaxf(mx, oth[j]);
        float e[5], se = 0.f;
        #pragma unroll
        for (int j = 0; j < 5; j++) { e[j] = __expf(q[j] - mx); se += e[j]; }
        const float tot = se + __shfl_xor_sync(0xffffffffu, se, 16);
        const float rt = 1.0f / tot;
        #pragma unroll
        for (int j = 0; j < 5; j++) sacc[j] += (e[j] * rt) * h[j];
    }
    float* sp = g_spart + ((size_t)b * NT + blockIdx.x) * OD;
    #pragma unroll
    for (int j = 0; j < 5; j++) sp[j * 32 + lane] = sacc[j];
}

// K3: reduce partials in fixed order, squash, update vsum (or write final out)
__global__ void __launch_bounds__(256) k_squash(float* __restrict__ out, int final_pass) {
    const int t = threadIdx.x;
    const int g = blockIdx.x * 16 + (t >> 4);   // (b,o) group id, 2560 total
    const int d = t & 15;
    const int b = g / OO, o = g % OO;

    float s = 0.f;
    const int od = o * DDO + d;
    for (int tt = 0; tt < NT; tt++)
        s += g_spart[((size_t)b * NT + tt) * OD + od];

    float ss = s * s;
    #pragma unroll
    for (int sh = 8; sh >= 1; sh >>= 1)
        ss += __shfl_xor_sync(0xffffffffu, ss, sh);

    const float nrm = sqrtf(ss);
    const float scale = nrm / (nrm * nrm + 1.0f);
    const float v = s * scale;
    const int idx = b * OD + od;
    if (final_pass) out[idx] = v;
    else g_vsum[idx] += v;
}

extern "C" void kernel_launch(void* const* d_in, const int* in_sizes, int n_in,
                              void* d_out, int out_size) {
    const float* x = (const float*)d_in[0];   // (B, I, DI)
    const float* w = (const float*)d_in[1];   // (I*O, DO, DI)
    float* out = (float*)d_out;               // (B, O, DO)

    dim3 grid(NT, BB / BW);

    k_zero<<<40, 1024>>>();
    k_hat<<<grid, 256>>>(x, w);
    k_squash<<<160, 256>>>(out, 0);   // v0 -> vsum
    k_route<<<grid, 256>>>();         // iter 1
    k_squash<<<160, 256>>>(out, 0);   // v1 -> vsum
    k_route<<<grid, 256>>>();         // iter 2
    k_squash<<<160, 256>>>(out, 1);   // v2 -> out
}

// round 3
// speedup vs baseline: 1.3059x; 1.3059x over previous
#include <cuda_runtime.h>
#include <cuda_bf16.h>

#define BB 256
#define II 1152
#define OO 10
#define DDO 16
#define DDI 8
#define OD 160       // OO*DDO
#define WPAD 12      // smem W row stride (floats), conflict-free LDS.128

// k_hat tiling
#define ITH 16       // i per block (hat)
#define NTH 72       // II/ITH
#define RPT 4        // i staged per sync round
// k_route tiling
#define ITR 32       // i per block (route)
#define NTR 36       // II/ITR
#define BW 8         // warps per block
#define NTMAX 72     // g_spart tile stride

// Scratch (device globals: allocation-free rule)
__device__ __nv_bfloat16 g_hat[(size_t)BB * II * OD];   // ~94.4 MB
__device__ float g_spart[(size_t)BB * NTMAX * OD];
__device__ float g_vsum[BB * OD];

// K1: hat_u = W @ x per (b,i); write g_hat (bf16); partial s0 = 0.1*sum hat
__global__ void __launch_bounds__(256) k_hat(const float* __restrict__ x,
                                             const float* __restrict__ w) {
    __shared__ float wsm[RPT * 1920];
    const int t = threadIdx.x;
    const int warp = t >> 5, lane = t & 31;
    const int og = lane >> 4, d = lane & 15;
    const int i0 = blockIdx.x * ITH;
    const int b0 = (blockIdx.y * BW + warp) * 2;   // 2 batches per thread

    float sacc0[5] = {0.f,0.f,0.f,0.f,0.f};
    float sacc1[5] = {0.f,0.f,0.f,0.f,0.f};

    for (int rr = 0; rr < ITH / RPT; rr++) {
        const int ib = i0 + rr * RPT;
        // stage W for RPT i's
        #pragma unroll
        for (int im = 0; im < RPT; im++) {
            const float* wp = w + (size_t)(ib + im) * (OD * DDI);
            float* ws = wsm + im * 1920;
            #pragma unroll
            for (int r = 0; r < 5; r++) {
                int e = t + r * 256;
                ws[(e >> 3) * WPAD + (e & 7)] = wp[e];
            }
        }
        __syncthreads();

        #pragma unroll
        for (int im = 0; im < RPT; im++) {
            const int i = ib + im;
            const float* xp0 = x + ((size_t)b0 * II + i) * DDI;
            const float* xp1 = x + ((size_t)(b0 + 1) * II + i) * DDI;
            const float4 xa0 = *(const float4*)xp0;
            const float4 xb0 = *(const float4*)(xp0 + 4);
            const float4 xa1 = *(const float4*)xp1;
            const float4 xb1 = *(const float4*)(xp1 + 4);
            const float* base = wsm + im * 1920;

            __nv_bfloat16* hp0 = g_hat + ((size_t)b0 * II + i) * OD;
            __nv_bfloat16* hp1 = g_hat + ((size_t)(b0 + 1) * II + i) * OD;

            #pragma unroll
            for (int j = 0; j < 5; j++) {
                const int o = og + 2 * j;
                const float* wr = base + (o * DDO + d) * WPAD;
                const float4 wa = *(const float4*)wr;
                const float4 wb = *(const float4*)(wr + 4);
                float h0 = wa.x*xa0.x + wa.y*xa0.y + wa.z*xa0.z + wa.w*xa0.w
                         + wb.x*xb0.x + wb.y*xb0.y + wb.z*xb0.z + wb.w*xb0.w;
                float h1 = wa.x*xa1.x + wa.y*xa1.y + wa.z*xa1.z + wa.w*xa1.w
                         + wb.x*xb1.x + wb.y*xb1.y + wb.z*xb1.z + wb.w*xb1.w;
                sacc0[j] += h0;
                sacc1[j] += h1;
                hp0[j * 32 + lane] = __float2bfloat16(h0);
                hp1[j * 32 + lane] = __float2bfloat16(h1);
            }
        }
        __syncthreads();
    }
    float* sp0 = g_spart + ((size_t)b0 * NTMAX + blockIdx.x) * OD;
    float* sp1 = g_spart + ((size_t)(b0 + 1) * NTMAX + blockIdx.x) * OD;
    #pragma unroll
    for (int j = 0; j < 5; j++) {
        sp0[j * 32 + lane] = 0.1f * sacc0[j];
        sp1[j * 32 + lane] = 0.1f * sacc1[j];
    }
}

// K2: routing pass. logits = hat.vsum ; c = softmax_o (no max-sub, logits tiny);
// s_partial += c * hat
__global__ void __launch_bounds__(256) k_route() {
    __shared__ float vs[BW][OD];
    const int t = threadIdx.x;
    const int warp = t >> 5, lane = t & 31;
    const int b0 = blockIdx.y * BW;
    const int b = b0 + warp;
    const int i0 = blockIdx.x * ITR;

    for (int m = t; m < BW * OD; m += 256) vs[m / OD][m % OD] = g_vsum[b0 * OD + m];
    __syncthreads();

    float vv[5];
    #pragma unroll
    for (int j = 0; j < 5; j++) vv[j] = vs[warp][j * 32 + lane];

    float sacc[5] = {0.f,0.f,0.f,0.f,0.f};

    for (int ii = 0; ii < ITR; ii++) {
        const __nv_bfloat16* hp = g_hat + ((size_t)b * II + (i0 + ii)) * OD;
        float h[5], q[5];
        #pragma unroll
        for (int j = 0; j < 5; j++) h[j] = __bfloat162float(__ldg(&hp[j * 32 + lane]));
        #pragma unroll
        for (int j = 0; j < 5; j++) q[j] = h[j] * vv[j];
        // reduce over d within each 16-lane half
        #pragma unroll
        for (int s = 8; s >= 1; s >>= 1) {
            #pragma unroll
            for (int j = 0; j < 5; j++)
                q[j] += __shfl_xor_sync(0xffffffffu, q[j], s);
        }
        // unstabilized softmax (|logit| <= ~2.5)
        float e[5], se = 0.f;
        #pragma unroll
        for (int j = 0; j < 5; j++) { e[j] = __expf(q[j]); se += e[j]; }
        const float tot = se + __shfl_xor_sync(0xffffffffu, se, 16);
        const float rt = 1.0f / tot;
        #pragma unroll
        for (int j = 0; j < 5; j++) sacc[j] += (e[j] * rt) * h[j];
    }
    float* sp = g_spart + ((size_t)b * NTMAX + blockIdx.x) * OD;
    #pragma unroll
    for (int j = 0; j < 5; j++) sp[j * 32 + lane] = sacc[j];
}

// K3: fixed-order partial reduction, squash.
// mode 0: vsum = v ; mode 1: vsum += v ; mode 2: out = v
__global__ void __launch_bounds__(256) k_squash(float* __restrict__ out, int mode,
                                                int ntiles) {
    const int t = threadIdx.x;
    const int g = blockIdx.x * 16 + (t >> 4);
    const int d = t & 15;
    const int b = g / OO, o = g % OO;

    float s = 0.f;
    const int od = o * DDO + d;
    for (int tt = 0; tt < ntiles; tt++)
        s += g_spart[((size_t)b * NTMAX + tt) * OD + od];

    float ss = s * s;
    #pragma unroll
    for (int sh = 8; sh >= 1; sh >>= 1)
        ss += __shfl_xor_sync(0xffffffffu, ss, sh);

    const float nrm = sqrtf(ss);
    const float scale = nrm / (nrm * nrm + 1.0f);
    const float v = s * scale;
    const int idx = b * OD + od;
    if (mode == 2)      out[idx] = v;
    else if (mode == 1) g_vsum[idx] += v;
    else                g_vsum[idx] = v;
}

extern "C" void kernel_launch(void* const* d_in, const int* in_sizes, int n_in,
                              void* d_out, int out_size) {
    const float* x = (const float*)d_in[0];   // (B, I, DI)
    const float* w = (const float*)d_in[1];   // (I*O, DO, DI)
    float* out = (float*)d_out;               // (B, O, DO)

    dim3 ghat(NTH, BB / (BW * 2));
    dim3 grt(NTR, BB / BW);

    k_hat<<<ghat, 256>>>(x, w);
    k_squash<<<160, 256>>>(out, 0, NTH);   // v0 -> vsum
    k_route<<<grt, 256>>>();               // iter 1
    k_squash<<<160, 256>>>(out, 1, NTR);   // v1 -> vsum
    k_route<<<grt, 256>>>();               // iter 2
    k_squash<<<160, 256>>>(out, 2, NTR);   // v2 -> out
}

// round 5
// speedup vs baseline: 1.7673x; 1.3533x over previous
#include <cuda_runtime.h>
#include <cuda_fp16.h>

#define BB 256
#define II 1152
#define OO 10
#define DDO 16
#define DDI 8
#define OD 160       // OO*DDO
#define WPAD 12      // smem W row stride (floats), conflict-free LDS.128

// k_hat tiling
#define ITH 16       // i per block (hat)
#define NTH 72       // II/ITH
#define RPT 4        // i staged per sync round
#define NBH 4        // batches per warp (hat)
// k_route tiling
#define ITR 32       // i per block (route)
#define NTR 36       // II/ITR
#define NTMAX 72     // g_spart tile stride

// Scratch (device globals: allocation-free rule)
__device__ __half g_hat[(size_t)BB * II * OD];    // ~94.4 MB
__device__ float g_spart[(size_t)BB * NTMAX * OD];
__device__ float g_vsum[BB * OD];

// K1: hat_u = W @ x per (b,i); write g_hat (fp16); partial s0 = 0.1*sum hat
__global__ void __launch_bounds__(256) k_hat(const float* __restrict__ x,
                                             const float* __restrict__ w) {
    __shared__ float wsm[RPT * 1920];
    const int t = threadIdx.x;
    const int warp = t >> 5, lane = t & 31;
    const int og = lane >> 4, d = lane & 15;
    const int i0 = blockIdx.x * ITH;
    const int b0 = (blockIdx.y * 8 + warp) * NBH;   // 4 batches per warp

    float sacc[NBH][5];
    #pragma unroll
    for (int bi = 0; bi < NBH; bi++)
        #pragma unroll
        for (int j = 0; j < 5; j++) sacc[bi][j] = 0.f;

    for (int rr = 0; rr < ITH / RPT; rr++) {
        const int ib = i0 + rr * RPT;
        #pragma unroll
        for (int im = 0; im < RPT; im++) {
            const float* wp = w + (size_t)(ib + im) * (OD * DDI);
            float* ws = wsm + im * 1920;
            #pragma unroll
            for (int r = 0; r < 5; r++) {
                int e = t + r * 256;
                ws[(e >> 3) * WPAD + (e & 7)] = wp[e];
            }
        }
        __syncthreads();

        #pragma unroll
        for (int im = 0; im < RPT; im++) {
            const int i = ib + im;
            float4 xa[NBH], xb[NBH];
            #pragma unroll
            for (int bi = 0; bi < NBH; bi++) {
                const float* xp = x + ((size_t)(b0 + bi) * II + i) * DDI;
                xa[bi] = *(const float4*)xp;
                xb[bi] = *(const float4*)(xp + 4);
            }
            const float* base = wsm + im * 1920;
            __half* hp = g_hat + ((size_t)b0 * II + i) * OD;

            #pragma unroll
            for (int j = 0; j < 5; j++) {
                const int o = og + 2 * j;
                const float* wr = base + (o * DDO + d) * WPAD;
                const float4 wa = *(const float4*)wr;
                const float4 wb = *(const float4*)(wr + 4);
                #pragma unroll
                for (int bi = 0; bi < NBH; bi++) {
                    float h = wa.x*xa[bi].x + wa.y*xa[bi].y + wa.z*xa[bi].z + wa.w*xa[bi].w
                            + wb.x*xb[bi].x + wb.y*xb[bi].y + wb.z*xb[bi].z + wb.w*xb[bi].w;
                    sacc[bi][j] += h;
                    hp[(size_t)bi * (II * OD) + j * 32 + lane] = __float2half_rn(h);
                }
            }
        }
        __syncthreads();
    }
    #pragma unroll
    for (int bi = 0; bi < NBH; bi++) {
        float* sp = g_spart + ((size_t)(b0 + bi) * NTMAX + blockIdx.x) * OD;
        #pragma unroll
        for (int j = 0; j < 5; j++) sp[j * 32 + lane] = 0.1f * sacc[bi][j];
    }
}

// K2: routing pass, o-per-lane layout. Lane = (bh, o): lanes 0-9 & 16-25 active,
// each active lane owns a full hat row slice h[o][0..15] in registers.
__global__ void __launch_bounds__(256) k_route() {
    const int t = threadIdx.x;
    const int warp = t >> 5, lane = t & 31;
    const int o = lane & 15;
    const bool act = (o < OO);
    const int b = blockIdx.y * 16 + warp * 2 + (lane >> 4);
    const int i0 = blockIdx.x * ITR;

    // per-lane v[o][0..15]
    float v[16];
    const float* vp = g_vsum + b * OD + o * DDO;
    if (act) {
        #pragma unroll
        for (int r = 0; r < 4; r++) {
            float4 f = *(const float4*)(vp + 4 * r);
            v[4*r] = f.x; v[4*r+1] = f.y; v[4*r+2] = f.z; v[4*r+3] = f.w;
        }
    } else {
        #pragma unroll
        for (int k = 0; k < 16; k++) v[k] = 0.f;
    }

    float sacc[16];
    #pragma unroll
    for (int k = 0; k < 16; k++) sacc[k] = 0.f;

    for (int ii = 0; ii < ITR; ii++) {
        const __half* hp = g_hat + ((size_t)b * II + (i0 + ii)) * OD + o * DDO;
        float h[16];
        float e = 0.f;
        if (act) {
            uint4 ra = *(const uint4*)hp;          // halfs 0..7
            uint4 rb = *(const uint4*)(hp + 8);    // halfs 8..15
            const __half2* pa = (const __half2*)&ra;
            const __half2* pb = (const __half2*)&rb;
            #pragma unroll
            for (int k = 0; k < 4; k++) {
                float2 fa = __half22float2(pa[k]);
                float2 fb = __half22float2(pb[k]);
                h[2*k]     = fa.x; h[2*k+1]     = fa.y;
                h[8+2*k]   = fb.x; h[8+2*k+1]   = fb.y;
            }
            float q = 0.f;
            #pragma unroll
            for (int k = 0; k < 16; k++) q += h[k] * v[k];
            e = __expf(q);                          // unstabilized, |q| small
        } else {
            #pragma unroll
            for (int k = 0; k < 16; k++) h[k] = 0.f;
        }
        float tot = e;
        #pragma unroll
        for (int s = 8; s >= 1; s >>= 1)
            tot += __shfl_xor_sync(0xffffffffu, tot, s);
        const float c = e * (1.0f / tot);
        #pragma unroll
        for (int k = 0; k < 16; k++) sacc[k] += c * h[k];
    }

    if (act) {
        float* sp = g_spart + ((size_t)b * NTMAX + blockIdx.x) * OD + o * DDO;
        #pragma unroll
        for (int r = 0; r < 4; r++)
            *(float4*)(sp + 4 * r) = make_float4(sacc[4*r], sacc[4*r+1],
                                                 sacc[4*r+2], sacc[4*r+3]);
    }
}

// K3: fixed-order partial reduction + squash. Warp per (b,o); lane = (tc, d).
__global__ void __launch_bounds__(256) k_squash(float* __restrict__ out, int mode,
                                                int ntiles) {
    const int t = threadIdx.x;
    const int warp = t >> 5, lane = t & 31;
    const int g = blockIdx.x * 8 + warp;       // (b,o) group, 2560 total
    const int d = lane & 15, tc = lane >> 4;
    const int b = g / OO, o = g - b * OO;
    const int od = o * DDO + d;

    float sh = 0.f;
    for (int tt = tc; tt < ntiles; tt += 2)
        sh += g_spart[((size_t)b * NTMAX + tt) * OD + od];
    const float s = sh + __shfl_xor_sync(0xffffffffu, sh, 16);

    float ss = s * s;
    #pragma unroll
    for (int r = 8; r >= 1; r >>= 1)
        ss += __shfl_xor_sync(0xffffffffu, ss, r);

    const float nrm = sqrtf(ss);
    const float v = s * (nrm / (nrm * nrm + 1.0f));
    if (tc == 0) {
        const int idx = b * OD + od;
        if (mode == 2)      out[idx] = v;
        else if (mode == 1) g_vsum[idx] += v;
        else                g_vsum[idx] = v;
    }
}

extern "C" void kernel_launch(void* const* d_in, const int* in_sizes, int n_in,
                              void* d_out, int out_size) {
    const float* x = (const float*)d_in[0];   // (B, I, DI)
    const float* w = (const float*)d_in[1];   // (I*O, DO, DI)
    float* out = (float*)d_out;               // (B, O, DO)

    dim3 ghat(NTH, BB / (8 * NBH));
    dim3 grt(NTR, BB / 16);

    k_hat<<<ghat, 256>>>(x, w);
    k_squash<<<320, 256>>>(out, 0, NTH);   // v0 -> vsum
    k_route<<<grt, 256>>>();               // iter 1
    k_squash<<<320, 256>>>(out, 1, NTR);   // v1 -> vsum
    k_route<<<grt, 256>>>();               // iter 2
    k_squash<<<320, 256>>>(out, 2, NTR);   // v2 -> out
}